// round 6
// baseline (speedup 1.0000x reference)
#include <cuda_runtime.h>

// Problem constants
#define S_LEN   1024
#define DK      64
#define BH      96
#define M_TILE  64
#define NTHREADS 256

#define CTX_ELEMS  ((size_t)BH * S_LEN * DK)        // 6,291,456
#define ATTN_ELEMS ((size_t)BH * S_LEN * S_LEN)     // 100,663,296

// Mask dtype mode, set by detector kernel: 0=int32, 1=float32, 2=uint8
__device__ int g_mask_mode;

// Packed mask bits, written in pass A, read (L2-hot) in pass B.
// Layout: word = ((cta*8 + warp)*16 + kt)*16 + j*4 + {0..3}; bit = lane.
// 1536 CTAs * 2048 words = 12.58 MB.
__device__ __align__(16) unsigned g_maskbits[1536 * 2048];

__global__ void detect_mask_kernel(const unsigned int* __restrict__ m) {
    int lane = threadIdx.x;
    unsigned no = 0, nf = 0, ni = 0;
    for (int i = lane; i < 1024; i += 32) {
        unsigned w = m[i];
        if (w == 0u) continue;
        if (w == 0x3F800000u) nf = 1;
        else if (w == 1u)     ni = 1;
        else                  no = 1;
    }
    unsigned bno = __ballot_sync(0xFFFFFFFFu, no != 0);
    unsigned bnf = __ballot_sync(0xFFFFFFFFu, nf != 0);
    unsigned bni = __ballot_sync(0xFFFFFFFFu, ni != 0);
    if (lane == 0) {
        int mode;
        if (bno)              mode = 2;   // bytes pack >1 word values -> uint8 bools
        else if (bnf && !bni) mode = 1;   // only 0.0f/1.0f patterns -> float32
        else                  mode = 0;   // only 0/1 ints -> int32
        g_mask_mode = mode;
    }
}

__device__ __forceinline__ unsigned f2tf(float f) {
    unsigned u;
    asm("cvt.rna.tf32.f32 %0, %1;" : "=r"(u) : "f"(f));
    return u;
}

__device__ __forceinline__ void mma_tf32(float c[4], const unsigned a[4],
                                         unsigned b0, unsigned b1) {
    asm volatile(
        "mma.sync.aligned.m16n8k8.row.col.f32.tf32.tf32.f32 "
        "{%0,%1,%2,%3}, {%4,%5,%6,%7}, {%8,%9}, {%0,%1,%2,%3};\n"
        : "+f"(c[0]), "+f"(c[1]), "+f"(c[2]), "+f"(c[3])
        : "r"(a[0]), "r"(a[1]), "r"(a[2]), "r"(a[3]), "r"(b0), "r"(b1));
}

// Fused masked attention, recompute-QK^T design (no attn round-trip):
//   pass A: S = QK^T/8, p = mask?0:exp(S) -> row sums + packed mask bits only
//   pass B: recompute S, p_norm = exp(S)/rowsum -> single attn write (streaming),
//           P staged in smem as tf32, P@V via MMA
__global__ __launch_bounds__(NTHREADS)
void attn_kernel(const float* __restrict__ Q, const float* __restrict__ K,
                 const float* __restrict__ V, const void* __restrict__ maskp,
                 float* __restrict__ ctx_out, float* __restrict__ attn_out)
{
    // s_a: K tile (stride 68; banks (4n+kk)%32 unique for score B-frags) and,
    //      after the score MMA in pass B, the P tile (stride 68; banks
    //      (4g+t)%32 unique for PV A-frags).
    // s_v: V tile (stride 72; banks (8kk+n)%32 unique for PV B-frags).
    __shared__ __align__(16) unsigned s_a[64 * 68];
    __shared__ __align__(16) unsigned s_v[64 * 72];
    __shared__ float s_rowsum[64];
    __shared__ float s_inv[64];

    const int tid  = threadIdx.x;
    const int w    = tid >> 5;
    const int lane = tid & 31;
    const int mr   = w & 3;        // row group: rows mr*16 .. +15
    const int nc   = w >> 2;       // col group: cols nc*32 .. +31
    const int g    = lane >> 2;    // groupID
    const int t    = lane & 3;     // threadID-in-group
    const int bh    = blockIdx.y;
    const int qbase = blockIdx.x * M_TILE;
    const int mode  = g_mask_mode;

    const size_t qkv_base = (size_t)bh * S_LEN * DK;
    const size_t attn_bh  = (size_t)bh * S_LEN * S_LEN;
    const unsigned mb_cta = ((unsigned)(bh * 16 + blockIdx.x) * 8 + w) * 256; // *16kt*16

    const unsigned char* mu8  = (const unsigned char*)maskp;
    const int*           mi32 = (const int*)maskp;
    const float*         mf32 = (const float*)maskp;

    // ---- Q A-fragments (tf32), reused by both passes -----------------------
    unsigned qa[8][4];
    {
        const float* Qp = Q + qkv_base + (size_t)(qbase + mr * 16) * DK;
        #pragma unroll
        for (int ki = 0; ki < 8; ++ki) {
            int c0 = ki * 8 + t;
            qa[ki][0] = f2tf(Qp[g * DK + c0]);
            qa[ki][1] = f2tf(Qp[(g + 8) * DK + c0]);
            qa[ki][2] = f2tf(Qp[g * DK + c0 + 4]);
            qa[ki][3] = f2tf(Qp[(g + 8) * DK + c0 + 4]);
        }
    }

    if (tid < 64) s_rowsum[tid] = 0.f;

    const int row0c = mr * 16 + g;       // CTA-relative row of c0/c1
    const int grow0 = qbase + row0c;     // absolute q row
    float rs0 = 0.f, rs1 = 0.f;

    // ======================= PASS A: row sums + mask bits ===================
    for (int kt = 0; kt < 16; ++kt) {
        __syncthreads();
        {   // stage K tile [64 keys x 64 d] as tf32 bits, stride 68
            const float* Kp = K + qkv_base + (size_t)(kt * 64) * DK;
            #pragma unroll
            for (int i = 0; i < 4; ++i) {
                int fidx = i * NTHREADS + tid;
                int r = fidx >> 4, c4 = (fidx & 15) * 4;
                float4 v = *(const float4*)(Kp + r * DK + c4);
                *(uint4*)&s_a[r * 68 + c4] =
                    make_uint4(f2tf(v.x), f2tf(v.y), f2tf(v.z), f2tf(v.w));
            }
        }
        __syncthreads();

        float sc[4][4];
        #pragma unroll
        for (int j = 0; j < 4; ++j) { sc[j][0]=0.f; sc[j][1]=0.f; sc[j][2]=0.f; sc[j][3]=0.f; }

        #pragma unroll
        for (int ki = 0; ki < 8; ++ki) {
            int kk = ki * 8 + t;
            #pragma unroll
            for (int j = 0; j < 4; ++j) {
                int n = nc * 32 + j * 8 + g;
                unsigned b0 = s_a[n * 68 + kk];
                unsigned b1 = s_a[n * 68 + kk + 4];
                mma_tf32(sc[j], qa[ki], b0, b1);
            }
        }

        // epilogue: mask (streaming loads), exp, row sums, pack mask bits
        #pragma unroll
        for (int j = 0; j < 4; ++j) {
            int col = kt * 64 + nc * 32 + j * 8 + 2 * t;
            size_t off0 = attn_bh + (size_t)grow0 * S_LEN + col;
            size_t off1 = off0 + (size_t)8 * S_LEN;
            unsigned m0, m1, m2, m3;
            if (mode == 2) {
                unsigned short a = __ldcs((const unsigned short*)(mu8 + off0));
                unsigned short b = __ldcs((const unsigned short*)(mu8 + off1));
                m0 = a & 0xFFu; m1 = a >> 8;
                m2 = b & 0xFFu; m3 = b >> 8;
            } else if (mode == 0) {
                int2 a = __ldcs((const int2*)(mi32 + off0));
                int2 b = __ldcs((const int2*)(mi32 + off1));
                m0 = (unsigned)a.x; m1 = (unsigned)a.y;
                m2 = (unsigned)b.x; m3 = (unsigned)b.y;
            } else {
                float2 a = __ldcs((const float2*)(mf32 + off0));
                float2 b = __ldcs((const float2*)(mf32 + off1));
                m0 = (a.x != 0.f); m1 = (a.y != 0.f);
                m2 = (b.x != 0.f); m3 = (b.y != 0.f);
            }
            unsigned w0 = __ballot_sync(0xFFFFFFFFu, m0 != 0);
            unsigned w1 = __ballot_sync(0xFFFFFFFFu, m1 != 0);
            unsigned w2 = __ballot_sync(0xFFFFFFFFu, m2 != 0);
            unsigned w3 = __ballot_sync(0xFFFFFFFFu, m3 != 0);
            if (lane == 0)
                *(uint4*)&g_maskbits[mb_cta + kt * 16 + j * 4] =
                    make_uint4(w0, w1, w2, w3);
            float p0 = m0 ? 0.f : __expf(sc[j][0] * 0.125f);
            float p1 = m1 ? 0.f : __expf(sc[j][1] * 0.125f);
            float p2 = m2 ? 0.f : __expf(sc[j][2] * 0.125f);
            float p3 = m3 ? 0.f : __expf(sc[j][3] * 0.125f);
            rs0 += p0 + p1;
            rs1 += p2 + p3;
        }
    }

    // row-sum reduce: quad (same row) -> smem across the 2 col-group warps
    rs0 += __shfl_xor_sync(0xFFFFFFFFu, rs0, 1);
    rs0 += __shfl_xor_sync(0xFFFFFFFFu, rs0, 2);
    rs1 += __shfl_xor_sync(0xFFFFFFFFu, rs1, 1);
    rs1 += __shfl_xor_sync(0xFFFFFFFFu, rs1, 2);
    if (t == 0) {
        atomicAdd(&s_rowsum[row0c], rs0);
        atomicAdd(&s_rowsum[row0c + 8], rs1);
    }
    __syncthreads();
    if (tid < 64) s_inv[tid] = 1.0f / s_rowsum[tid];
    __syncthreads();

    const float inv0 = s_inv[row0c];
    const float inv1 = s_inv[row0c + 8];

    // ======================= PASS B: recompute + attn write + PV ============
    float oc[4][4];
    #pragma unroll
    for (int j = 0; j < 4; ++j) { oc[j][0]=0.f; oc[j][1]=0.f; oc[j][2]=0.f; oc[j][3]=0.f; }

    for (int kt = 0; kt < 16; ++kt) {
        __syncthreads();   // previous PV MMA done reading s_a/s_v
        {   // stage K tile -> s_a (stride 68) and V tile -> s_v (stride 72)
            const float* Kp = K + qkv_base + (size_t)(kt * 64) * DK;
            const float* Vp = V + qkv_base + (size_t)(kt * 64) * DK;
            #pragma unroll
            for (int i = 0; i < 4; ++i) {
                int fidx = i * NTHREADS + tid;
                int r = fidx >> 4, c4 = (fidx & 15) * 4;
                float4 kv = *(const float4*)(Kp + r * DK + c4);
                *(uint4*)&s_a[r * 68 + c4] =
                    make_uint4(f2tf(kv.x), f2tf(kv.y), f2tf(kv.z), f2tf(kv.w));
                float4 vv = *(const float4*)(Vp + r * DK + c4);
                *(uint4*)&s_v[r * 72 + c4] =
                    make_uint4(f2tf(vv.x), f2tf(vv.y), f2tf(vv.z), f2tf(vv.w));
            }
        }
        __syncthreads();

        float sc[4][4];
        #pragma unroll
        for (int j = 0; j < 4; ++j) { sc[j][0]=0.f; sc[j][1]=0.f; sc[j][2]=0.f; sc[j][3]=0.f; }

        #pragma unroll
        for (int ki = 0; ki < 8; ++ki) {
            int kk = ki * 8 + t;
            #pragma unroll
            for (int j = 0; j < 4; ++j) {
                int n = nc * 32 + j * 8 + g;
                unsigned b0 = s_a[n * 68 + kk];
                unsigned b1 = s_a[n * 68 + kk + 4];
                mma_tf32(sc[j], qa[ki], b0, b1);
            }
        }
        __syncthreads();   // all warps done reading K before P overwrites s_a

        // epilogue: mask bits (L2-hot broadcast), normalize, single attn write,
        // stash normalized P (tf32) into s_a for the PV MMA
        const unsigned bit = 1u << lane;
        #pragma unroll
        for (int j = 0; j < 4; ++j) {
            int col_l = nc * 32 + j * 8 + 2 * t;       // CTA-local column
            int col   = kt * 64 + col_l;
            size_t off0 = attn_bh + (size_t)grow0 * S_LEN + col;
            size_t off1 = off0 + (size_t)8 * S_LEN;
            uint4 mw = *(const uint4*)&g_maskbits[mb_cta + kt * 16 + j * 4];
            float p0 = (mw.x & bit) ? 0.f : __expf(sc[j][0] * 0.125f) * inv0;
            float p1 = (mw.y & bit) ? 0.f : __expf(sc[j][1] * 0.125f) * inv0;
            float p2 = (mw.z & bit) ? 0.f : __expf(sc[j][2] * 0.125f) * inv1;
            float p3 = (mw.w & bit) ? 0.f : __expf(sc[j][3] * 0.125f) * inv1;
            __stcs((float2*)(attn_out + off0), make_float2(p0, p1));
            __stcs((float2*)(attn_out + off1), make_float2(p2, p3));
            *(uint2*)&s_a[row0c * 68 + col_l]       = make_uint2(f2tf(p0), f2tf(p1));
            *(uint2*)&s_a[(row0c + 8) * 68 + col_l] = make_uint2(f2tf(p2), f2tf(p3));
        }
        __syncthreads();

        #pragma unroll
        for (int ki = 0; ki < 8; ++ki) {
            int kk = ki * 8 + t;
            unsigned a[4];
            a[0] = s_a[(mr * 16 + g) * 68 + kk];
            a[1] = s_a[(mr * 16 + g + 8) * 68 + kk];
            a[2] = s_a[(mr * 16 + g) * 68 + kk + 4];
            a[3] = s_a[(mr * 16 + g + 8) * 68 + kk + 4];
            #pragma unroll
            for (int j = 0; j < 4; ++j) {
                int n = nc * 32 + j * 8 + g;
                unsigned b0 = s_v[kk * 72 + n];
                unsigned b1 = s_v[(kk + 4) * 72 + n];
                mma_tf32(oc[j], a, b0, b1);
            }
        }
    }

    // ---- write context -----------------------------------------------------
    const size_t cb = qkv_base + (size_t)grow0 * DK;
    #pragma unroll
    for (int j = 0; j < 4; ++j) {
        int dcol = nc * 32 + j * 8 + 2 * t;
        *(float2*)(ctx_out + cb + dcol)          = make_float2(oc[j][0], oc[j][1]);
        *(float2*)(ctx_out + cb + 8 * DK + dcol) = make_float2(oc[j][2], oc[j][3]);
    }
}

extern "C" void kernel_launch(void* const* d_in, const int* in_sizes, int n_in,
                              void* d_out, int out_size) {
    const float* Q = (const float*)d_in[0];
    const float* K = (const float*)d_in[1];
    const float* V = (const float*)d_in[2];
    const void*  M = d_in[3];

    float* ctx  = (float*)d_out;                 // tuple order: (context, attn)
    float* attn = (float*)d_out + CTX_ELEMS;

    detect_mask_kernel<<<1, 32>>>((const unsigned int*)M);

    dim3 grid(S_LEN / M_TILE, BH);               // (16, 96)
    attn_kernel<<<grid, NTHREADS>>>(Q, K, V, M, ctx, attn);
}

// round 8
// speedup vs baseline: 1.0656x; 1.0656x over previous
#include <cuda_runtime.h>

// Problem constants
#define S_LEN   1024
#define DK      64
#define BH      96
#define M_TILE  64
#define NTHREADS 256

#define CTX_ELEMS  ((size_t)BH * S_LEN * DK)        // 6,291,456

// Mask dtype mode, set by detector kernel: 0=int32, 1=float32, 2=uint8
__device__ int g_mask_mode;

// Packed mask bits, written by rowsum kernel, read (L2-hot-ish) by output kernel.
// word = ((cta*8 + warp)*16 + kt)*16 + j*4 + {0..3}; bit = lane.  12.58 MB.
__device__ __align__(16) unsigned g_maskbits[1536 * 2048];
// 1/rowsum per (bh, row).  384 KB.
__device__ float g_inv[BH * S_LEN];

__global__ void detect_mask_kernel(const unsigned int* __restrict__ m) {
    int lane = threadIdx.x;
    unsigned no = 0, nf = 0, ni = 0;
    for (int i = lane; i < 1024; i += 32) {
        unsigned w = m[i];
        if (w == 0u) continue;
        if (w == 0x3F800000u) nf = 1;
        else if (w == 1u)     ni = 1;
        else                  no = 1;
    }
    unsigned bno = __ballot_sync(0xFFFFFFFFu, no != 0);
    unsigned bnf = __ballot_sync(0xFFFFFFFFu, nf != 0);
    unsigned bni = __ballot_sync(0xFFFFFFFFu, ni != 0);
    if (lane == 0) {
        int mode;
        if (bno)              mode = 2;   // uint8 bools
        else if (bnf && !bni) mode = 1;   // float32 0.0/1.0
        else                  mode = 0;   // int32 0/1
        g_mask_mode = mode;
    }
}

__device__ __forceinline__ unsigned f2tf(float f) {
    unsigned u;
    asm("cvt.rna.tf32.f32 %0, %1;" : "=r"(u) : "f"(f));
    return u;
}

__device__ __forceinline__ void mma_tf32(float c[4], const unsigned a[4],
                                         unsigned b0, unsigned b1) {
    asm volatile(
        "mma.sync.aligned.m16n8k8.row.col.f32.tf32.tf32.f32 "
        "{%0,%1,%2,%3}, {%4,%5,%6,%7}, {%8,%9}, {%0,%1,%2,%3};\n"
        : "+f"(c[0]), "+f"(c[1]), "+f"(c[2]), "+f"(c[3])
        : "r"(a[0]), "r"(a[1]), "r"(a[2]), "r"(a[3]), "r"(b0), "r"(b1));
}

// ========================= KERNEL A: rowsums + mask bits ====================
__global__ __launch_bounds__(NTHREADS, 3)
void rowsum_kernel(const float* __restrict__ Q, const float* __restrict__ K,
                   const void* __restrict__ maskp)
{
    __shared__ __align__(16) unsigned s_k[64 * 68];  // stride 68: (4n+kk)%32 unique
    __shared__ float s_rowsum[64];

    const int tid  = threadIdx.x;
    const int w    = tid >> 5;
    const int lane = tid & 31;
    const int mr   = w & 3;
    const int nc   = w >> 2;
    const int g    = lane >> 2;
    const int t    = lane & 3;
    const int bh    = blockIdx.y;
    const int qbase = blockIdx.x * M_TILE;
    const int mode  = g_mask_mode;

    const size_t qkv_base = (size_t)bh * S_LEN * DK;
    const size_t attn_bh  = (size_t)bh * S_LEN * S_LEN;
    const unsigned mb_cta = ((unsigned)(bh * 16 + blockIdx.x) * 8 + w) * 256;

    const unsigned char* mu8  = (const unsigned char*)maskp;
    const int*           mi32 = (const int*)maskp;
    const float*         mf32 = (const float*)maskp;

    // Q A-fragments (tf32) in registers
    unsigned qa[8][4];
    {
        const float* Qp = Q + qkv_base + (size_t)(qbase + mr * 16) * DK;
        #pragma unroll
        for (int ki = 0; ki < 8; ++ki) {
            int c0 = ki * 8 + t;
            qa[ki][0] = f2tf(Qp[g * DK + c0]);
            qa[ki][1] = f2tf(Qp[(g + 8) * DK + c0]);
            qa[ki][2] = f2tf(Qp[g * DK + c0 + 4]);
            qa[ki][3] = f2tf(Qp[(g + 8) * DK + c0 + 4]);
        }
    }

    if (tid < 64) s_rowsum[tid] = 0.f;

    const int row0c = mr * 16 + g;
    const int grow0 = qbase + row0c;
    float rs0 = 0.f, rs1 = 0.f;

    for (int kt = 0; kt < 16; ++kt) {
        __syncthreads();
        {   // stage K tile as tf32 bits
            const float* Kp = K + qkv_base + (size_t)(kt * 64) * DK;
            #pragma unroll
            for (int i = 0; i < 4; ++i) {
                int fidx = i * NTHREADS + tid;
                int r = fidx >> 4, c4 = (fidx & 15) * 4;
                float4 v = *(const float4*)(Kp + r * DK + c4);
                *(uint4*)&s_k[r * 68 + c4] =
                    make_uint4(f2tf(v.x), f2tf(v.y), f2tf(v.z), f2tf(v.w));
            }
        }
        __syncthreads();

        float sc[4][4];
        #pragma unroll
        for (int j = 0; j < 4; ++j) { sc[j][0]=0.f; sc[j][1]=0.f; sc[j][2]=0.f; sc[j][3]=0.f; }

        #pragma unroll
        for (int ki = 0; ki < 8; ++ki) {
            int kk = ki * 8 + t;
            #pragma unroll
            for (int j = 0; j < 4; ++j) {
                int n = nc * 32 + j * 8 + g;
                mma_tf32(sc[j], qa[ki], s_k[n * 68 + kk], s_k[n * 68 + kk + 4]);
            }
        }

        // mask (streaming), pack bits, exp, row sums
        #pragma unroll
        for (int j = 0; j < 4; ++j) {
            int col = kt * 64 + nc * 32 + j * 8 + 2 * t;
            size_t off0 = attn_bh + (size_t)grow0 * S_LEN + col;
            size_t off1 = off0 + (size_t)8 * S_LEN;
            unsigned m0, m1, m2, m3;
            if (mode == 2) {
                unsigned short a = __ldcs((const unsigned short*)(mu8 + off0));
                unsigned short b = __ldcs((const unsigned short*)(mu8 + off1));
                m0 = a & 0xFFu; m1 = a >> 8;
                m2 = b & 0xFFu; m3 = b >> 8;
            } else if (mode == 0) {
                int2 a = __ldcs((const int2*)(mi32 + off0));
                int2 b = __ldcs((const int2*)(mi32 + off1));
                m0 = (unsigned)a.x; m1 = (unsigned)a.y;
                m2 = (unsigned)b.x; m3 = (unsigned)b.y;
            } else {
                float2 a = __ldcs((const float2*)(mf32 + off0));
                float2 b = __ldcs((const float2*)(mf32 + off1));
                m0 = (a.x != 0.f); m1 = (a.y != 0.f);
                m2 = (b.x != 0.f); m3 = (b.y != 0.f);
            }
            unsigned w0 = __ballot_sync(0xFFFFFFFFu, m0 != 0);
            unsigned w1 = __ballot_sync(0xFFFFFFFFu, m1 != 0);
            unsigned w2 = __ballot_sync(0xFFFFFFFFu, m2 != 0);
            unsigned w3 = __ballot_sync(0xFFFFFFFFu, m3 != 0);
            if (lane == 0)
                *(uint4*)&g_maskbits[mb_cta + kt * 16 + j * 4] =
                    make_uint4(w0, w1, w2, w3);
            float p0 = m0 ? 0.f : __expf(sc[j][0] * 0.125f);
            float p1 = m1 ? 0.f : __expf(sc[j][1] * 0.125f);
            float p2 = m2 ? 0.f : __expf(sc[j][2] * 0.125f);
            float p3 = m3 ? 0.f : __expf(sc[j][3] * 0.125f);
            rs0 += p0 + p1;
            rs1 += p2 + p3;
        }
    }

    rs0 += __shfl_xor_sync(0xFFFFFFFFu, rs0, 1);
    rs0 += __shfl_xor_sync(0xFFFFFFFFu, rs0, 2);
    rs1 += __shfl_xor_sync(0xFFFFFFFFu, rs1, 1);
    rs1 += __shfl_xor_sync(0xFFFFFFFFu, rs1, 2);
    if (t == 0) {
        atomicAdd(&s_rowsum[row0c], rs0);
        atomicAdd(&s_rowsum[row0c + 8], rs1);
    }
    __syncthreads();
    if (tid < 64)
        g_inv[bh * S_LEN + qbase + tid] = 1.0f / s_rowsum[tid];
}

// ========================= KERNEL B: attn write + PV ========================
// Dynamic smem layout (70,656 B):
//   s_q [64*68]  Q tile tf32   (A-frag loads: banks (4g+t)%32 unique)
//   s_k [64*68]  K tile tf32   (B-frag loads: banks (4n+kk)%32 unique)
//   s_v [64*72]  V tile tf32   (B-frag loads: banks (8kk+n)%32 unique)
//   s_p [64*68]  normalized P  (A-frag loads: banks (4g+t)%32 unique)
#define SQ_OFF 0
#define SK_OFF (64 * 68)
#define SV_OFF (2 * 64 * 68)
#define SP_OFF (2 * 64 * 68 + 64 * 72)
#define SMEM_B_BYTES ((3 * 64 * 68 + 64 * 72) * 4)

__global__ __launch_bounds__(NTHREADS, 3)
void attn_out_kernel(const float* __restrict__ Q, const float* __restrict__ K,
                     const float* __restrict__ V,
                     float* __restrict__ ctx_out, float* __restrict__ attn_out)
{
    extern __shared__ __align__(16) unsigned smem[];
    unsigned* s_q = smem + SQ_OFF;
    unsigned* s_k = smem + SK_OFF;
    unsigned* s_v = smem + SV_OFF;
    unsigned* s_p = smem + SP_OFF;

    const int tid  = threadIdx.x;
    const int w    = tid >> 5;
    const int lane = tid & 31;
    const int mr   = w & 3;
    const int nc   = w >> 2;
    const int g    = lane >> 2;
    const int t    = lane & 3;
    const int bh    = blockIdx.y;
    const int qbase = blockIdx.x * M_TILE;

    const size_t qkv_base = (size_t)bh * S_LEN * DK;
    const size_t attn_bh  = (size_t)bh * S_LEN * S_LEN;
    const unsigned mb_cta = ((unsigned)(bh * 16 + blockIdx.x) * 8 + w) * 256;

    const int row0c = mr * 16 + g;
    const int grow0 = qbase + row0c;

    // stage Q tile once (tf32 bits)
    {
        const float* Qp = Q + qkv_base + (size_t)qbase * DK;
        #pragma unroll
        for (int i = 0; i < 4; ++i) {
            int fidx = i * NTHREADS + tid;
            int r = fidx >> 4, c4 = (fidx & 15) * 4;
            float4 v = *(const float4*)(Qp + r * DK + c4);
            *(uint4*)&s_q[r * 68 + c4] =
                make_uint4(f2tf(v.x), f2tf(v.y), f2tf(v.z), f2tf(v.w));
        }
    }

    const float inv0 = g_inv[bh * S_LEN + grow0];
    const float inv1 = g_inv[bh * S_LEN + grow0 + 8];
    const unsigned bit = 1u << lane;

    float oc[4][4];
    #pragma unroll
    for (int j = 0; j < 4; ++j) { oc[j][0]=0.f; oc[j][1]=0.f; oc[j][2]=0.f; oc[j][3]=0.f; }

    for (int kt = 0; kt < 16; ++kt) {
        __syncthreads();   // prev PV done with s_p/s_v; s_k free; (first iter: Q staged)
        {   // stage K -> s_k, V -> s_v
            const float* Kp = K + qkv_base + (size_t)(kt * 64) * DK;
            const float* Vp = V + qkv_base + (size_t)(kt * 64) * DK;
            #pragma unroll
            for (int i = 0; i < 4; ++i) {
                int fidx = i * NTHREADS + tid;
                int r = fidx >> 4, c4 = (fidx & 15) * 4;
                float4 kv = *(const float4*)(Kp + r * DK + c4);
                *(uint4*)&s_k[r * 68 + c4] =
                    make_uint4(f2tf(kv.x), f2tf(kv.y), f2tf(kv.z), f2tf(kv.w));
                float4 vv = *(const float4*)(Vp + r * DK + c4);
                *(uint4*)&s_v[r * 72 + c4] =
                    make_uint4(f2tf(vv.x), f2tf(vv.y), f2tf(vv.z), f2tf(vv.w));
            }
        }
        __syncthreads();

        // QK^T (A-frags from s_q)
        float sc[4][4];
        #pragma unroll
        for (int j = 0; j < 4; ++j) { sc[j][0]=0.f; sc[j][1]=0.f; sc[j][2]=0.f; sc[j][3]=0.f; }

        #pragma unroll
        for (int ki = 0; ki < 8; ++ki) {
            int kk = ki * 8 + t;
            unsigned a[4];
            a[0] = s_q[row0c * 68 + kk];
            a[1] = s_q[(row0c + 8) * 68 + kk];
            a[2] = s_q[row0c * 68 + kk + 4];
            a[3] = s_q[(row0c + 8) * 68 + kk + 4];
            #pragma unroll
            for (int j = 0; j < 4; ++j) {
                int n = nc * 32 + j * 8 + g;
                mma_tf32(sc[j], a, s_k[n * 68 + kk], s_k[n * 68 + kk + 4]);
            }
        }

        // epilogue: mask bits, normalize, single streaming attn write, P -> s_p
        #pragma unroll
        for (int j = 0; j < 4; ++j) {
            int col_l = nc * 32 + j * 8 + 2 * t;
            size_t off0 = attn_bh + (size_t)grow0 * S_LEN + kt * 64 + col_l;
            size_t off1 = off0 + (size_t)8 * S_LEN;
            uint4 mw = *(const uint4*)&g_maskbits[mb_cta + kt * 16 + j * 4];
            float p0 = (mw.x & bit) ? 0.f : __expf(sc[j][0] * 0.125f) * inv0;
            float p1 = (mw.y & bit) ? 0.f : __expf(sc[j][1] * 0.125f) * inv0;
            float p2 = (mw.z & bit) ? 0.f : __expf(sc[j][2] * 0.125f) * inv1;
            float p3 = (mw.w & bit) ? 0.f : __expf(sc[j][3] * 0.125f) * inv1;
            __stcs((float2*)(attn_out + off0), make_float2(p0, p1));
            __stcs((float2*)(attn_out + off1), make_float2(p2, p3));
            *(uint2*)&s_p[row0c * 68 + col_l]       = make_uint2(f2tf(p0), f2tf(p1));
            *(uint2*)&s_p[(row0c + 8) * 68 + col_l] = make_uint2(f2tf(p2), f2tf(p3));
        }
        __syncthreads();   // all P written before cross-warp PV reads

        // PV (A-frags from s_p)
        #pragma unroll
        for (int ki = 0; ki < 8; ++ki) {
            int kk = ki * 8 + t;
            unsigned a[4];
            a[0] = s_p[row0c * 68 + kk];
            a[1] = s_p[(row0c + 8) * 68 + kk];
            a[2] = s_p[row0c * 68 + kk + 4];
            a[3] = s_p[(row0c + 8) * 68 + kk + 4];
            #pragma unroll
            for (int j = 0; j < 4; ++j) {
                int n = nc * 32 + j * 8 + g;
                mma_tf32(oc[j], a, s_v[kk * 72 + n], s_v[(kk + 4) * 72 + n]);
            }
        }
    }

    // write context
    const size_t cb = qkv_base + (size_t)grow0 * DK;
    #pragma unroll
    for (int j = 0; j < 4; ++j) {
        int dcol = nc * 32 + j * 8 + 2 * t;
        *(float2*)(ctx_out + cb + dcol)          = make_float2(oc[j][0], oc[j][1]);
        *(float2*)(ctx_out + cb + 8 * DK + dcol) = make_float2(oc[j][2], oc[j][3]);
    }
}

extern "C" void kernel_launch(void* const* d_in, const int* in_sizes, int n_in,
                              void* d_out, int out_size) {
    const float* Q = (const float*)d_in[0];
    const float* K = (const float*)d_in[1];
    const float* V = (const float*)d_in[2];
    const void*  M = d_in[3];

    float* ctx  = (float*)d_out;                 // tuple order: (context, attn)
    float* attn = (float*)d_out + CTX_ELEMS;

    // idempotent; legal during graph capture (host-side attribute, no alloc/sync)
    cudaFuncSetAttribute(attn_out_kernel,
                         cudaFuncAttributeMaxDynamicSharedMemorySize, SMEM_B_BYTES);

    detect_mask_kernel<<<1, 32>>>((const unsigned int*)M);

    dim3 grid(S_LEN / M_TILE, BH);               // (16, 96)
    rowsum_kernel<<<grid, NTHREADS>>>(Q, K, M);
    attn_out_kernel<<<grid, NTHREADS, SMEM_B_BYTES>>>(Q, K, V, ctx, attn);
}

// round 9
// speedup vs baseline: 1.0667x; 1.0011x over previous
#include <cuda_runtime.h>

// Problem constants
#define S_LEN   1024
#define DK      64
#define BH      96
#define M_TILE  64
#define NTHREADS 256

#define CTX_ELEMS  ((size_t)BH * S_LEN * DK)        // 6,291,456

// Mask dtype mode, set by detector kernel: 0=int32, 1=float32, 2=uint8
__device__ int g_mask_mode;

// Packed mask bits, written by rowsum kernel, read (L2-hot-ish) by output kernel.
// word = ((cta*8 + warp)*16 + kt)*16 + j*4 + {0..3}; bit = lane.  12.58 MB.
__device__ __align__(16) unsigned g_maskbits[1536 * 2048];
// 1/rowsum per (bh, row).  384 KB.
__device__ float g_inv[BH * S_LEN];

__global__ void detect_mask_kernel(const unsigned int* __restrict__ m) {
    int lane = threadIdx.x;
    unsigned no = 0, nf = 0, ni = 0;
    for (int i = lane; i < 1024; i += 32) {
        unsigned w = m[i];
        if (w == 0u) continue;
        if (w == 0x3F800000u) nf = 1;
        else if (w == 1u)     ni = 1;
        else                  no = 1;
    }
    unsigned bno = __ballot_sync(0xFFFFFFFFu, no != 0);
    unsigned bnf = __ballot_sync(0xFFFFFFFFu, nf != 0);
    unsigned bni = __ballot_sync(0xFFFFFFFFu, ni != 0);
    if (lane == 0) {
        int mode;
        if (bno)              mode = 2;   // uint8 bools
        else if (bnf && !bni) mode = 1;   // float32 0.0/1.0
        else                  mode = 0;   // int32 0/1
        g_mask_mode = mode;
    }
}

__device__ __forceinline__ unsigned f2tf(float f) {
    unsigned u;
    asm("cvt.rna.tf32.f32 %0, %1;" : "=r"(u) : "f"(f));
    return u;
}

__device__ __forceinline__ void mma_tf32(float c[4], const unsigned a[4],
                                         unsigned b0, unsigned b1) {
    asm volatile(
        "mma.sync.aligned.m16n8k8.row.col.f32.tf32.tf32.f32 "
        "{%0,%1,%2,%3}, {%4,%5,%6,%7}, {%8,%9}, {%0,%1,%2,%3};\n"
        : "+f"(c[0]), "+f"(c[1]), "+f"(c[2]), "+f"(c[3])
        : "r"(a[0]), "r"(a[1]), "r"(a[2]), "r"(a[3]), "r"(b0), "r"(b1));
}

// ========================= KERNEL A: rowsums + mask bits ====================
__global__ __launch_bounds__(NTHREADS, 3)
void rowsum_kernel(const float* __restrict__ Q, const float* __restrict__ K,
                   const void* __restrict__ maskp)
{
    __shared__ __align__(16) unsigned s_k[64 * 68];  // stride 68: (4n+kk)%32 unique
    __shared__ float s_rowsum[64];

    const int tid  = threadIdx.x;
    const int w    = tid >> 5;
    const int lane = tid & 31;
    const int mr   = w & 3;
    const int nc   = w >> 2;
    const int g    = lane >> 2;
    const int t    = lane & 3;
    const int bh    = blockIdx.y;
    const int qbase = blockIdx.x * M_TILE;
    const int mode  = g_mask_mode;

    const size_t qkv_base = (size_t)bh * S_LEN * DK;
    const size_t attn_bh  = (size_t)bh * S_LEN * S_LEN;
    const unsigned mb_cta = ((unsigned)(bh * 16 + blockIdx.x) * 8 + w) * 256;

    const unsigned char* mu8  = (const unsigned char*)maskp;
    const int*           mi32 = (const int*)maskp;
    const float*         mf32 = (const float*)maskp;

    // Q A-fragments (tf32) in registers
    unsigned qa[8][4];
    {
        const float* Qp = Q + qkv_base + (size_t)(qbase + mr * 16) * DK;
        #pragma unroll
        for (int ki = 0; ki < 8; ++ki) {
            int c0 = ki * 8 + t;
            qa[ki][0] = f2tf(Qp[g * DK + c0]);
            qa[ki][1] = f2tf(Qp[(g + 8) * DK + c0]);
            qa[ki][2] = f2tf(Qp[g * DK + c0 + 4]);
            qa[ki][3] = f2tf(Qp[(g + 8) * DK + c0 + 4]);
        }
    }

    if (tid < 64) s_rowsum[tid] = 0.f;

    const int row0c = mr * 16 + g;
    const int grow0 = qbase + row0c;
    float rs0 = 0.f, rs1 = 0.f;

    for (int kt = 0; kt < 16; ++kt) {
        __syncthreads();
        {   // stage K tile as tf32 bits
            const float* Kp = K + qkv_base + (size_t)(kt * 64) * DK;
            #pragma unroll
            for (int i = 0; i < 4; ++i) {
                int fidx = i * NTHREADS + tid;
                int r = fidx >> 4, c4 = (fidx & 15) * 4;
                float4 v = *(const float4*)(Kp + r * DK + c4);
                *(uint4*)&s_k[r * 68 + c4] =
                    make_uint4(f2tf(v.x), f2tf(v.y), f2tf(v.z), f2tf(v.w));
            }
        }
        __syncthreads();

        float sc[4][4];
        #pragma unroll
        for (int j = 0; j < 4; ++j) { sc[j][0]=0.f; sc[j][1]=0.f; sc[j][2]=0.f; sc[j][3]=0.f; }

        #pragma unroll
        for (int ki = 0; ki < 8; ++ki) {
            int kk = ki * 8 + t;
            #pragma unroll
            for (int j = 0; j < 4; ++j) {
                int n = nc * 32 + j * 8 + g;
                mma_tf32(sc[j], qa[ki], s_k[n * 68 + kk], s_k[n * 68 + kk + 4]);
            }
        }

        // mask (streaming), pack bits, exp, row sums
        #pragma unroll
        for (int j = 0; j < 4; ++j) {
            int col = kt * 64 + nc * 32 + j * 8 + 2 * t;
            size_t off0 = attn_bh + (size_t)grow0 * S_LEN + col;
            size_t off1 = off0 + (size_t)8 * S_LEN;
            unsigned m0, m1, m2, m3;
            if (mode == 2) {
                unsigned short a = __ldcs((const unsigned short*)(mu8 + off0));
                unsigned short b = __ldcs((const unsigned short*)(mu8 + off1));
                m0 = a & 0xFFu; m1 = a >> 8;
                m2 = b & 0xFFu; m3 = b >> 8;
            } else if (mode == 0) {
                int2 a = __ldcs((const int2*)(mi32 + off0));
                int2 b = __ldcs((const int2*)(mi32 + off1));
                m0 = (unsigned)a.x; m1 = (unsigned)a.y;
                m2 = (unsigned)b.x; m3 = (unsigned)b.y;
            } else {
                float2 a = __ldcs((const float2*)(mf32 + off0));
                float2 b = __ldcs((const float2*)(mf32 + off1));
                m0 = (a.x != 0.f); m1 = (a.y != 0.f);
                m2 = (b.x != 0.f); m3 = (b.y != 0.f);
            }
            unsigned w0 = __ballot_sync(0xFFFFFFFFu, m0 != 0);
            unsigned w1 = __ballot_sync(0xFFFFFFFFu, m1 != 0);
            unsigned w2 = __ballot_sync(0xFFFFFFFFu, m2 != 0);
            unsigned w3 = __ballot_sync(0xFFFFFFFFu, m3 != 0);
            if (lane == 0)
                *(uint4*)&g_maskbits[mb_cta + kt * 16 + j * 4] =
                    make_uint4(w0, w1, w2, w3);
            float p0 = m0 ? 0.f : __expf(sc[j][0] * 0.125f);
            float p1 = m1 ? 0.f : __expf(sc[j][1] * 0.125f);
            float p2 = m2 ? 0.f : __expf(sc[j][2] * 0.125f);
            float p3 = m3 ? 0.f : __expf(sc[j][3] * 0.125f);
            rs0 += p0 + p1;
            rs1 += p2 + p3;
        }
    }

    rs0 += __shfl_xor_sync(0xFFFFFFFFu, rs0, 1);
    rs0 += __shfl_xor_sync(0xFFFFFFFFu, rs0, 2);
    rs1 += __shfl_xor_sync(0xFFFFFFFFu, rs1, 1);
    rs1 += __shfl_xor_sync(0xFFFFFFFFu, rs1, 2);
    if (t == 0) {
        atomicAdd(&s_rowsum[row0c], rs0);
        atomicAdd(&s_rowsum[row0c + 8], rs1);
    }
    __syncthreads();
    if (tid < 64)
        g_inv[bh * S_LEN + qbase + tid] = 1.0f / s_rowsum[tid];
}

// ========================= KERNEL B: attn write + PV ========================
// Dynamic smem layout (70,656 B):
//   s_q [64*68]  Q tile tf32   (A-frag loads: banks (4g+t)%32 unique)
//   s_k [64*68]  K tile tf32   (B-frag loads: banks (4n+kk)%32 unique)
//   s_v [64*72]  V tile tf32   (B-frag loads: banks (8kk+n)%32 unique)
//   s_p [64*68]  normalized P  (A-frag loads: banks (4g+t)%32 unique)
#define SQ_OFF 0
#define SK_OFF (64 * 68)
#define SV_OFF (2 * 64 * 68)
#define SP_OFF (2 * 64 * 68 + 64 * 72)
#define SMEM_B_BYTES ((3 * 64 * 68 + 64 * 72) * 4)

__global__ __launch_bounds__(NTHREADS, 3)
void attn_out_kernel(const float* __restrict__ Q, const float* __restrict__ K,
                     const float* __restrict__ V,
                     float* __restrict__ ctx_out, float* __restrict__ attn_out)
{
    extern __shared__ __align__(16) unsigned smem[];
    unsigned* s_q = smem + SQ_OFF;
    unsigned* s_k = smem + SK_OFF;
    unsigned* s_v = smem + SV_OFF;
    unsigned* s_p = smem + SP_OFF;

    const int tid  = threadIdx.x;
    const int w    = tid >> 5;
    const int lane = tid & 31;
    const int mr   = w & 3;
    const int nc   = w >> 2;
    const int g    = lane >> 2;
    const int t    = lane & 3;
    const int bh    = blockIdx.y;
    const int qbase = blockIdx.x * M_TILE;

    const size_t qkv_base = (size_t)bh * S_LEN * DK;
    const size_t attn_bh  = (size_t)bh * S_LEN * S_LEN;
    const unsigned mb_cta = ((unsigned)(bh * 16 + blockIdx.x) * 8 + w) * 256;

    const int row0c = mr * 16 + g;
    const int grow0 = qbase + row0c;

    // stage Q tile once (tf32 bits)
    {
        const float* Qp = Q + qkv_base + (size_t)qbase * DK;
        #pragma unroll
        for (int i = 0; i < 4; ++i) {
            int fidx = i * NTHREADS + tid;
            int r = fidx >> 4, c4 = (fidx & 15) * 4;
            float4 v = *(const float4*)(Qp + r * DK + c4);
            *(uint4*)&s_q[r * 68 + c4] =
                make_uint4(f2tf(v.x), f2tf(v.y), f2tf(v.z), f2tf(v.w));
        }
    }

    const float inv0 = g_inv[bh * S_LEN + grow0];
    const float inv1 = g_inv[bh * S_LEN + grow0 + 8];
    const unsigned bit = 1u << lane;

    float oc[4][4];
    #pragma unroll
    for (int j = 0; j < 4; ++j) { oc[j][0]=0.f; oc[j][1]=0.f; oc[j][2]=0.f; oc[j][3]=0.f; }

    for (int kt = 0; kt < 16; ++kt) {
        __syncthreads();   // prev PV done with s_p/s_v; s_k free; (first iter: Q staged)
        {   // stage K -> s_k, V -> s_v
            const float* Kp = K + qkv_base + (size_t)(kt * 64) * DK;
            const float* Vp = V + qkv_base + (size_t)(kt * 64) * DK;
            #pragma unroll
            for (int i = 0; i < 4; ++i) {
                int fidx = i * NTHREADS + tid;
                int r = fidx >> 4, c4 = (fidx & 15) * 4;
                float4 kv = *(const float4*)(Kp + r * DK + c4);
                *(uint4*)&s_k[r * 68 + c4] =
                    make_uint4(f2tf(kv.x), f2tf(kv.y), f2tf(kv.z), f2tf(kv.w));
                float4 vv = *(const float4*)(Vp + r * DK + c4);
                *(uint4*)&s_v[r * 72 + c4] =
                    make_uint4(f2tf(vv.x), f2tf(vv.y), f2tf(vv.z), f2tf(vv.w));
            }
        }
        __syncthreads();

        // QK^T (A-frags from s_q)
        float sc[4][4];
        #pragma unroll
        for (int j = 0; j < 4; ++j) { sc[j][0]=0.f; sc[j][1]=0.f; sc[j][2]=0.f; sc[j][3]=0.f; }

        #pragma unroll
        for (int ki = 0; ki < 8; ++ki) {
            int kk = ki * 8 + t;
            unsigned a[4];
            a[0] = s_q[row0c * 68 + kk];
            a[1] = s_q[(row0c + 8) * 68 + kk];
            a[2] = s_q[row0c * 68 + kk + 4];
            a[3] = s_q[(row0c + 8) * 68 + kk + 4];
            #pragma unroll
            for (int j = 0; j < 4; ++j) {
                int n = nc * 32 + j * 8 + g;
                mma_tf32(sc[j], a, s_k[n * 68 + kk], s_k[n * 68 + kk + 4]);
            }
        }

        // epilogue: mask bits, normalize, single streaming attn write, P -> s_p
        #pragma unroll
        for (int j = 0; j < 4; ++j) {
            int col_l = nc * 32 + j * 8 + 2 * t;
            size_t off0 = attn_bh + (size_t)grow0 * S_LEN + kt * 64 + col_l;
            size_t off1 = off0 + (size_t)8 * S_LEN;
            uint4 mw = *(const uint4*)&g_maskbits[mb_cta + kt * 16 + j * 4];
            float p0 = (mw.x & bit) ? 0.f : __expf(sc[j][0] * 0.125f) * inv0;
            float p1 = (mw.y & bit) ? 0.f : __expf(sc[j][1] * 0.125f) * inv0;
            float p2 = (mw.z & bit) ? 0.f : __expf(sc[j][2] * 0.125f) * inv1;
            float p3 = (mw.w & bit) ? 0.f : __expf(sc[j][3] * 0.125f) * inv1;
            __stcs((float2*)(attn_out + off0), make_float2(p0, p1));
            __stcs((float2*)(attn_out + off1), make_float2(p2, p3));
            *(uint2*)&s_p[row0c * 68 + col_l]       = make_uint2(f2tf(p0), f2tf(p1));
            *(uint2*)&s_p[(row0c + 8) * 68 + col_l] = make_uint2(f2tf(p2), f2tf(p3));
        }
        __syncthreads();   // all P written before cross-warp PV reads

        // PV (A-frags from s_p)
        #pragma unroll
        for (int ki = 0; ki < 8; ++ki) {
            int kk = ki * 8 + t;
            unsigned a[4];
            a[0] = s_p[row0c * 68 + kk];
            a[1] = s_p[(row0c + 8) * 68 + kk];
            a[2] = s_p[row0c * 68 + kk + 4];
            a[3] = s_p[(row0c + 8) * 68 + kk + 4];
            #pragma unroll
            for (int j = 0; j < 4; ++j) {
                int n = nc * 32 + j * 8 + g;
                mma_tf32(oc[j], a, s_v[kk * 72 + n], s_v[(kk + 4) * 72 + n]);
            }
        }
    }

    // write context
    const size_t cb = qkv_base + (size_t)grow0 * DK;
    #pragma unroll
    for (int j = 0; j < 4; ++j) {
        int dcol = nc * 32 + j * 8 + 2 * t;
        *(float2*)(ctx_out + cb + dcol)          = make_float2(oc[j][0], oc[j][1]);
        *(float2*)(ctx_out + cb + 8 * DK + dcol) = make_float2(oc[j][2], oc[j][3]);
    }
}

extern "C" void kernel_launch(void* const* d_in, const int* in_sizes, int n_in,
                              void* d_out, int out_size) {
    const float* Q = (const float*)d_in[0];
    const float* K = (const float*)d_in[1];
    const float* V = (const float*)d_in[2];
    const void*  M = d_in[3];

    float* ctx  = (float*)d_out;                 // tuple order: (context, attn)
    float* attn = (float*)d_out + CTX_ELEMS;

    // idempotent; legal during graph capture (host-side attribute, no alloc/sync)
    cudaFuncSetAttribute(attn_out_kernel,
                         cudaFuncAttributeMaxDynamicSharedMemorySize, SMEM_B_BYTES);

    detect_mask_kernel<<<1, 32>>>((const unsigned int*)M);

    dim3 grid(S_LEN / M_TILE, BH);               // (16, 96)
    rowsum_kernel<<<grid, NTHREADS>>>(Q, K, M);
    attn_out_kernel<<<grid, NTHREADS, SMEM_B_BYTES>>>(Q, K, V, ctx, attn);
}

// round 12
// speedup vs baseline: 1.2007x; 1.1256x over previous
#include <cuda_runtime.h>

// Problem constants
#define S_LEN   1024
#define DK      64
#define BH      96
#define NTHREADS 256
#define CTX_ELEMS ((size_t)BH * S_LEN * DK)

// ---- dynamic smem layout (words) ----
// region [0, 2*4608): K double-buffer (stride 68, 4352 words each, offsets 0 / 4352)
//                     V double-buffer (stride 72, 4608 words each, offsets 0 / 4608)
// region [9216, 9216+4352): s_p (normalized P, tf32 bits, stride 68)
#define KW    (64 * 68)          // 4352
#define VW    (64 * 72)          // 4608
#define OFF_P (2 * VW)           // 9216
#define SMEM_WORDS (2 * VW + 64 * 68)
#define SMEM_BYTES (SMEM_WORDS * 4)   // 54,272 B

__device__ __forceinline__ unsigned smem_u32(const void* p) {
    unsigned a;
    asm("{ .reg .u64 t; cvta.to.shared.u64 t, %1; cvt.u32.u64 %0, t; }"
        : "=r"(a) : "l"(p));
    return a;
}
__device__ __forceinline__ unsigned f2tf(float f) {
    unsigned u;
    asm("cvt.rna.tf32.f32 %0, %1;" : "=r"(u) : "f"(f));
    return u;
}
__device__ __forceinline__ void cp16(unsigned dst, const void* src) {
    asm volatile("cp.async.cg.shared.global [%0], [%1], 16;"
                 :: "r"(dst), "l"(src) : "memory");
}
#define CP_COMMIT() asm volatile("cp.async.commit_group;" ::: "memory")
#define CP_WAIT0()  asm volatile("cp.async.wait_group 0;" ::: "memory")

__device__ __forceinline__ void mma_tf32(float c[4], const unsigned a[4],
                                         unsigned b0, unsigned b1) {
    asm volatile(
        "mma.sync.aligned.m16n8k8.row.col.f32.tf32.tf32.f32 "
        "{%0,%1,%2,%3}, {%4,%5,%6,%7}, {%8,%9}, {%0,%1,%2,%3};\n"
        : "+f"(c[0]), "+f"(c[1]), "+f"(c[2]), "+f"(c[3])
        : "r"(a[0]), "r"(a[1]), "r"(a[2]), "r"(a[3]), "r"(b0), "r"(b1));
}

// Fused masked attention (R5 structure + cp.async double-buffer + inline RNA cvt):
//   pass 1: S = QK^T/8, p = mask?0:exp(S) -> unnormalized attn (streaming) + row sums
//   pass 2: read attn tile back, *1/rowsum, rewrite (streaming), P@V via MMA
__global__ __launch_bounds__(NTHREADS, 3)
void attn_kernel(const float* __restrict__ Q, const float* __restrict__ K,
                 const float* __restrict__ V, const void* __restrict__ maskp,
                 float* __restrict__ ctx_out, float* __restrict__ attn_out)
{
    extern __shared__ __align__(16) unsigned sm[];
    __shared__ float s_rowsum[64];
    __shared__ float s_inv[64];

    const int tid  = threadIdx.x;
    const int w    = tid >> 5;
    const int lane = tid & 31;
    const int mr   = w & 3;        // row group: rows mr*16 .. +15
    const int nc   = w >> 2;       // col group: cols nc*32 .. +31
    const int g    = lane >> 2;
    const int t    = lane & 3;
    const int bh    = blockIdx.y;
    const int qbase = blockIdx.x * 64;

    const size_t qkv_base = (size_t)bh * S_LEN * DK;
    const size_t attn_bh  = (size_t)bh * S_LEN * S_LEN;
    const unsigned smb = smem_u32(sm);

    if (tid < 64) s_rowsum[tid] = 0.f;

    // ---- mask dtype probe on first 4KB (word-sized 0/1/1.0f vs packed bytes)
    unsigned other = 0;
    {
        const unsigned* mw = (const unsigned*)maskp;
        #pragma unroll
        for (int i = 0; i < 4; ++i) {
            unsigned x = mw[tid * 4 + i];
            if (x != 0u && x != 1u && x != 0x3F800000u) other = 1;
        }
    }
    const int byte_mode = __syncthreads_or((int)other);

    const unsigned char* mu8  = (const unsigned char*)maskp;
    const int*           mwrd = (const int*)maskp;

    // ---- Q A-fragments (RNA tf32), reused for every key tile ---------------
    unsigned qa[8][4];
    {
        const float* Qp = Q + qkv_base + (size_t)(qbase + mr * 16) * DK;
        #pragma unroll
        for (int ki = 0; ki < 8; ++ki) {
            int c0 = ki * 8 + t;
            qa[ki][0] = f2tf(Qp[g * DK + c0]);
            qa[ki][1] = f2tf(Qp[(g + 8) * DK + c0]);
            qa[ki][2] = f2tf(Qp[g * DK + c0 + 4]);
            qa[ki][3] = f2tf(Qp[(g + 8) * DK + c0 + 4]);
        }
    }

    const int row0c = mr * 16 + g;
    const int grow0 = qbase + row0c;
    float rs0 = 0.f, rs1 = 0.f;

    // ---- prologue: prefetch K tile 0 into K-buf0 (raw fp32) ----------------
    {
        const float* Kp = K + qkv_base;
        #pragma unroll
        for (int i = 0; i < 4; ++i) {
            int f = i * NTHREADS + tid;
            int r = f >> 4, c = (f & 15) * 4;
            cp16(smb + (unsigned)(r * 68 + c) * 4, Kp + r * DK + c);
        }
        CP_COMMIT();
    }

    // ======================= PASS 1 ========================================
    for (int kt = 0; kt < 16; ++kt) {
        CP_WAIT0();            // my chunks of tile kt done (group committed last iter)
        __syncthreads();       // whole tile visible; all warps past MMA of kt-1
        const unsigned kb = (unsigned)(kt & 1) * KW;
        if (kt < 15) {         // prefetch tile kt+1 into the other buffer
            const float* Kp = K + qkv_base + (size_t)((kt + 1) * 64) * DK;
            const unsigned nb = (unsigned)((kt + 1) & 1) * KW;
            #pragma unroll
            for (int i = 0; i < 4; ++i) {
                int f = i * NTHREADS + tid;
                int r = f >> 4, c = (f & 15) * 4;
                cp16(smb + (nb + (unsigned)(r * 68 + c)) * 4, Kp + r * DK + c);
            }
            CP_COMMIT();
        }

        // QK^T: B-frags = raw fp32 from smem, RNA-converted inline
        float sc[4][4];
        #pragma unroll
        for (int j = 0; j < 4; ++j) { sc[j][0]=0.f; sc[j][1]=0.f; sc[j][2]=0.f; sc[j][3]=0.f; }

        #pragma unroll
        for (int ki = 0; ki < 8; ++ki) {
            int kk = ki * 8 + t;
            #pragma unroll
            for (int j = 0; j < 4; ++j) {
                int n = nc * 32 + j * 8 + g;
                unsigned b0 = f2tf(__uint_as_float(sm[kb + n * 68 + kk]));
                unsigned b1 = f2tf(__uint_as_float(sm[kb + n * 68 + kk + 4]));
                mma_tf32(sc[j], qa[ki], b0, b1);
            }
        }

        // epilogue: mask (streaming), exp, unnormalized attn store, row sums
        #pragma unroll
        for (int j = 0; j < 4; ++j) {
            int col = kt * 64 + nc * 32 + j * 8 + 2 * t;
            size_t off0 = attn_bh + (size_t)grow0 * S_LEN + col;
            size_t off1 = off0 + (size_t)8 * S_LEN;
            unsigned m0, m1, m2, m3;
            if (byte_mode) {
                unsigned short a = __ldcs((const unsigned short*)(mu8 + off0));
                unsigned short b = __ldcs((const unsigned short*)(mu8 + off1));
                m0 = a & 0xFFu; m1 = a >> 8;
                m2 = b & 0xFFu; m3 = b >> 8;
            } else {           // int32 (0/1) and float32 (0.0/1.0): word != 0
                int2 a = __ldcs((const int2*)(mwrd + off0));
                int2 b = __ldcs((const int2*)(mwrd + off1));
                m0 = (unsigned)a.x; m1 = (unsigned)a.y;
                m2 = (unsigned)b.x; m3 = (unsigned)b.y;
            }
            float p0 = m0 ? 0.f : __expf(sc[j][0] * 0.125f);
            float p1 = m1 ? 0.f : __expf(sc[j][1] * 0.125f);
            float p2 = m2 ? 0.f : __expf(sc[j][2] * 0.125f);
            float p3 = m3 ? 0.f : __expf(sc[j][3] * 0.125f);
            rs0 += p0 + p1;
            rs1 += p2 + p3;
            __stcs((float2*)(attn_out + off0), make_float2(p0, p1));
            __stcs((float2*)(attn_out + off1), make_float2(p2, p3));
        }
    }

    // ---- row-sum reduce (quad -> smem across the 2 col-group warps) --------
    rs0 += __shfl_xor_sync(0xFFFFFFFFu, rs0, 1);
    rs0 += __shfl_xor_sync(0xFFFFFFFFu, rs0, 2);
    rs1 += __shfl_xor_sync(0xFFFFFFFFu, rs1, 1);
    rs1 += __shfl_xor_sync(0xFFFFFFFFu, rs1, 2);
    if (t == 0) {
        atomicAdd(&s_rowsum[row0c], rs0);
        atomicAdd(&s_rowsum[row0c + 8], rs1);
    }
    __syncthreads();           // all warps past pass-1 MMAs (K buffers now free)

    // prefetch V tile 0 into V-buf0 (overlaps the inv computation)
    {
        const float* Vp = V + qkv_base;
        #pragma unroll
        for (int i = 0; i < 4; ++i) {
            int f = i * NTHREADS + tid;
            int r = f >> 4, c = (f & 15) * 4;
            cp16(smb + (unsigned)(r * 72 + c) * 4, Vp + r * DK + c);
        }
        CP_COMMIT();
    }
    if (tid < 64) s_inv[tid] = 1.0f / s_rowsum[tid];
    __syncthreads();

    // ======================= PASS 2 ========================================
    unsigned* s_p = sm + OFF_P;
    float oc[4][4];
    #pragma unroll
    for (int j = 0; j < 4; ++j) { oc[j][0]=0.f; oc[j][1]=0.f; oc[j][2]=0.f; oc[j][3]=0.f; }

    for (int kt = 0; kt < 16; ++kt) {
        CP_WAIT0();
        __syncthreads();       // V tile kt visible; all warps past PV of kt-1
        const unsigned vb = (unsigned)(kt & 1) * VW;
        if (kt < 15) {
            const float* Vp = V + qkv_base + (size_t)((kt + 1) * 64) * DK;
            const unsigned nb = (unsigned)((kt + 1) & 1) * VW;
            #pragma unroll
            for (int i = 0; i < 4; ++i) {
                int f = i * NTHREADS + tid;
                int r = f >> 4, c = (f & 15) * 4;
                cp16(smb + (nb + (unsigned)(r * 72 + c)) * 4, Vp + r * DK + c);
            }
            CP_COMMIT();
        }

        // read back unnormalized attn tile (streaming), normalize, rewrite,
        // stash RNA-tf32 P for the PV MMA
        {
            float* Ap = attn_out + attn_bh + (size_t)qbase * S_LEN + kt * 64;
            #pragma unroll
            for (int i = 0; i < 4; ++i) {
                int f = i * NTHREADS + tid;
                int r = f >> 4, c4 = (f & 15) * 4;
                float4 p4 = __ldcs((const float4*)(Ap + (size_t)r * S_LEN + c4));
                float iv = s_inv[r];
                p4.x *= iv; p4.y *= iv; p4.z *= iv; p4.w *= iv;
                __stcs((float4*)(Ap + (size_t)r * S_LEN + c4), p4);
                *(uint4*)&s_p[r * 68 + c4] =
                    make_uint4(f2tf(p4.x), f2tf(p4.y), f2tf(p4.z), f2tf(p4.w));
            }
        }
        __syncthreads();       // all P staged before cross-warp PV reads

        // PV: A-frags from s_p (tf32), B-frags = raw fp32 V, RNA inline
        #pragma unroll
        for (int ki = 0; ki < 8; ++ki) {
            int kk = ki * 8 + t;
            unsigned a[4];
            a[0] = s_p[row0c * 68 + kk];
            a[1] = s_p[(row0c + 8) * 68 + kk];
            a[2] = s_p[row0c * 68 + kk + 4];
            a[3] = s_p[(row0c + 8) * 68 + kk + 4];
            #pragma unroll
            for (int j = 0; j < 4; ++j) {
                int n = nc * 32 + j * 8 + g;
                unsigned b0 = f2tf(__uint_as_float(sm[vb + kk * 72 + n]));
                unsigned b1 = f2tf(__uint_as_float(sm[vb + (kk + 4) * 72 + n]));
                mma_tf32(oc[j], a, b0, b1);
            }
        }
    }

    // ---- write context -----------------------------------------------------
    const size_t cb = qkv_base + (size_t)grow0 * DK;
    #pragma unroll
    for (int j = 0; j < 4; ++j) {
        int dcol = nc * 32 + j * 8 + 2 * t;
        *(float2*)(ctx_out + cb + dcol)          = make_float2(oc[j][0], oc[j][1]);
        *(float2*)(ctx_out + cb + 8 * DK + dcol) = make_float2(oc[j][2], oc[j][3]);
    }
}

extern "C" void kernel_launch(void* const* d_in, const int* in_sizes, int n_in,
                              void* d_out, int out_size) {
    const float* Q = (const float*)d_in[0];
    const float* K = (const float*)d_in[1];
    const float* V = (const float*)d_in[2];
    const void*  M = d_in[3];

    float* ctx  = (float*)d_out;                 // tuple order: (context, attn)
    float* attn = (float*)d_out + CTX_ELEMS;

    cudaFuncSetAttribute(attn_kernel,
                         cudaFuncAttributeMaxDynamicSharedMemorySize, SMEM_BYTES);

    dim3 grid(S_LEN / 64, BH);                   // (16, 96)
    attn_kernel<<<grid, NTHREADS, SMEM_BYTES>>>(Q, K, V, M, ctx, attn);
}